// round 15
// baseline (speedup 1.0000x reference)
#include <cuda_runtime.h>
#include <math.h>

#define NSIDE 128
#define SLICES 1024
#define PLANE 16777216ull   // 1024 * 128 * 128

__device__ float2 g_Y1[SLICES * NSIDE * NSIDE];
__device__ float2 g_Y2[SLICES * NSIDE * NSIDE];

// ---------------------------------------------------------------------------
// Register/shuffle 128-pt FFT, batched NF-ways: 128 = 32 lanes x 4 regs.
// ---------------------------------------------------------------------------
struct Tw {
    float w16r, w16i, w8r, w8i, w4r, w4i, w2r, w2i;
    float c1, s1, c2, s2, c3, s3;
};

__device__ __forceinline__ void stage_tw(int t, int h, float& cr, float& ci)
{
    if (t & h) {
        sincospif(-(float)(t & (h - 1)) / (float)h, &ci, &cr);
    } else { cr = 1.0f; ci = 0.0f; }
}

__device__ __forceinline__ void make_tw(Tw& T, int t)
{
    int br = __brev(t) >> 27;
    sincospif((float)br * (1.0f / 64.0f), &T.s1, &T.c1);
    sincospif((float)br * (1.0f / 32.0f), &T.s2, &T.c2);
    sincospif((float)(3 * br) * (1.0f / 64.0f), &T.s3, &T.c3);
    stage_tw(t, 16, T.w16r, T.w16i);
    stage_tw(t, 8,  T.w8r,  T.w8i);
    stage_tw(t, 4,  T.w4r,  T.w4i);
    stage_tw(t, 2,  T.w2r,  T.w2i);
}

__device__ __forceinline__ void cmulm(float& ar, float& ai, float br, float bi)
{
    float r = ar * br - ai * bi;
    ai = ar * bi + ai * br;
    ar = r;
}

template <int NF, int H>
__device__ __forceinline__ void lstage_f(float (&vr)[NF][4], float (&vi)[NF][4],
                                         float twr, float twi, int t)
{
    float e = (t & H) ? -1.0f : 1.0f;
    float pr[NF][4], pi[NF][4];
#pragma unroll
    for (int f = 0; f < NF; ++f)
#pragma unroll
        for (int r = 0; r < 4; ++r) {
            pr[f][r] = __shfl_xor_sync(0xffffffffu, vr[f][r], H);
            pi[f][r] = __shfl_xor_sync(0xffffffffu, vi[f][r], H);
        }
#pragma unroll
    for (int f = 0; f < NF; ++f)
#pragma unroll
        for (int r = 0; r < 4; ++r) {
            float ur = fmaf(e, vr[f][r], pr[f][r]);
            float ui = fmaf(e, vi[f][r], pi[f][r]);
            vr[f][r] = ur * twr - ui * twi;
            vi[f][r] = fmaf(ur, twi, ui * twr);
        }
}

template <int NF>
__device__ __forceinline__ void lstage_f1(float (&vr)[NF][4], float (&vi)[NF][4], int t)
{
    float e = (t & 1) ? -1.0f : 1.0f;
    float pr[NF][4], pi[NF][4];
#pragma unroll
    for (int f = 0; f < NF; ++f)
#pragma unroll
        for (int r = 0; r < 4; ++r) {
            pr[f][r] = __shfl_xor_sync(0xffffffffu, vr[f][r], 1);
            pi[f][r] = __shfl_xor_sync(0xffffffffu, vi[f][r], 1);
        }
#pragma unroll
    for (int f = 0; f < NF; ++f)
#pragma unroll
        for (int r = 0; r < 4; ++r) {
            vr[f][r] = fmaf(e, vr[f][r], pr[f][r]);
            vi[f][r] = fmaf(e, vi[f][r], pi[f][r]);
        }
}

template <int NF, int H>
__device__ __forceinline__ void lstage_i(float (&vr)[NF][4], float (&vi)[NF][4],
                                         float twr, float twi, int t)
{
    float e = (t & H) ? -1.0f : 1.0f;
    float ar[NF][4], ai[NF][4], pr[NF][4], pi[NF][4];
#pragma unroll
    for (int f = 0; f < NF; ++f)
#pragma unroll
        for (int r = 0; r < 4; ++r) {
            ar[f][r] = fmaf(vi[f][r], twi, vr[f][r] * twr);
            ai[f][r] = vi[f][r] * twr - vr[f][r] * twi;
        }
#pragma unroll
    for (int f = 0; f < NF; ++f)
#pragma unroll
        for (int r = 0; r < 4; ++r) {
            pr[f][r] = __shfl_xor_sync(0xffffffffu, ar[f][r], H);
            pi[f][r] = __shfl_xor_sync(0xffffffffu, ai[f][r], H);
        }
#pragma unroll
    for (int f = 0; f < NF; ++f)
#pragma unroll
        for (int r = 0; r < 4; ++r) {
            vr[f][r] = fmaf(e, ar[f][r], pr[f][r]);
            vi[f][r] = fmaf(e, ai[f][r], pi[f][r]);
        }
}

template <int NF>
__device__ __forceinline__ void lstage_i1(float (&vr)[NF][4], float (&vi)[NF][4], int t)
{
    float e = (t & 1) ? -1.0f : 1.0f;
    float pr[NF][4], pi[NF][4];
#pragma unroll
    for (int f = 0; f < NF; ++f)
#pragma unroll
        for (int r = 0; r < 4; ++r) {
            pr[f][r] = __shfl_xor_sync(0xffffffffu, vr[f][r], 1);
            pi[f][r] = __shfl_xor_sync(0xffffffffu, vi[f][r], 1);
        }
#pragma unroll
    for (int f = 0; f < NF; ++f)
#pragma unroll
        for (int r = 0; r < 4; ++r) {
            vr[f][r] = fmaf(e, vr[f][r], pr[f][r]);
            vi[f][r] = fmaf(e, vi[f][r], pi[f][r]);
        }
}

template <int NF>
__device__ __forceinline__ void fft_fwd_n(float (&vr)[NF][4], float (&vi)[NF][4],
                                          const Tw& T, int t)
{
    lstage_f<NF, 16>(vr, vi, T.w16r, T.w16i, t);
    lstage_f<NF, 8>(vr, vi, T.w8r, T.w8i, t);
    lstage_f<NF, 4>(vr, vi, T.w4r, T.w4i, t);
    lstage_f<NF, 2>(vr, vi, T.w2r, T.w2i, t);
    lstage_f1<NF>(vr, vi, t);
#pragma unroll
    for (int f = 0; f < NF; ++f) {
        cmulm(vr[f][1], vi[f][1], T.c1, -T.s1);
        cmulm(vr[f][2], vi[f][2], T.c2, -T.s2);
        cmulm(vr[f][3], vi[f][3], T.c3, -T.s3);
        float s02r = vr[f][0] + vr[f][2], s02i = vi[f][0] + vi[f][2];
        float d02r = vr[f][0] - vr[f][2], d02i = vi[f][0] - vi[f][2];
        float s13r = vr[f][1] + vr[f][3], s13i = vi[f][1] + vi[f][3];
        float d13r = vr[f][1] - vr[f][3], d13i = vi[f][1] - vi[f][3];
        vr[f][0] = s02r + s13r; vi[f][0] = s02i + s13i;
        vr[f][2] = s02r - s13r; vi[f][2] = s02i - s13i;
        vr[f][1] = d02r + d13i; vi[f][1] = d02i - d13r;
        vr[f][3] = d02r - d13i; vi[f][3] = d02i + d13r;
    }
}

template <int NF>
__device__ __forceinline__ void fft_inv_n(float (&vr)[NF][4], float (&vi)[NF][4],
                                          const Tw& T, int t)
{
#pragma unroll
    for (int f = 0; f < NF; ++f) {
        float s02r = vr[f][0] + vr[f][2], s02i = vi[f][0] + vi[f][2];
        float d02r = vr[f][0] - vr[f][2], d02i = vi[f][0] - vi[f][2];
        float s13r = vr[f][1] + vr[f][3], s13i = vi[f][1] + vi[f][3];
        float d13r = vr[f][1] - vr[f][3], d13i = vi[f][1] - vi[f][3];
        vr[f][0] = s02r + s13r; vi[f][0] = s02i + s13i;
        vr[f][2] = s02r - s13r; vi[f][2] = s02i - s13i;
        vr[f][1] = d02r - d13i; vi[f][1] = d02i + d13r;
        vr[f][3] = d02r + d13i; vi[f][3] = d02i - d13r;
        cmulm(vr[f][1], vi[f][1], T.c1, T.s1);
        cmulm(vr[f][2], vi[f][2], T.c2, T.s2);
        cmulm(vr[f][3], vi[f][3], T.c3, T.s3);
    }
    lstage_i1<NF>(vr, vi, t);
    lstage_i<NF, 2>(vr, vi, T.w2r, T.w2i, t);
    lstage_i<NF, 4>(vr, vi, T.w4r, T.w4i, t);
    lstage_i<NF, 8>(vr, vi, T.w8r, T.w8i, t);
    lstage_i<NF, 16>(vr, vi, T.w16r, T.w16i, t);
}

__device__ __forceinline__ float fatan2f(float y, float x)
{
    float ax = fabsf(x), ay = fabsf(y);
    float mx = fmaxf(ax, ay), mn = fminf(ax, ay);
    float a = __fdividef(mn, mx);
    float s = a * a;
    float p = -0.0117212f;
    p = fmaf(p, s, 0.05265332f);
    p = fmaf(p, s, -0.11643287f);
    p = fmaf(p, s, 0.19354346f);
    p = fmaf(p, s, -0.33262347f);
    p = fmaf(p, s, 0.99997726f);
    float r = p * a;
    if (ay > ax) r = 1.57079632679f - r;
    if (x < 0.0f) r = 3.14159265359f - r;
    return copysignf(r, y);
}

__device__ __forceinline__ int st_of_kq(int kq)
{
    return (int)(__brev((unsigned)(kq & 31)) >> 27) + (kq & 96);
}

// ---------------------------------------------------------------------------
// P1: 256 threads, 3 CTAs/SM. Interleaved float2 half-spectrum smem.
// Column phase uses a single NF=4 batched inverse per unit (G1P,G1M,G2P,G2M).
// ---------------------------------------------------------------------------
__global__ void __launch_bounds__(256, 3) p1_kernel(const float* __restrict__ x)
{
    extern __shared__ float2 smc[];
    float2* F  = smc;           // 128*64 float2, row m stride 64
    float2* Ny = smc + 8192;    // 128 float2

    const int tid = threadIdx.x;
    const int s   = blockIdx.x;
    const int u   = tid >> 5;   // 0..7
    const int t   = tid & 31;

    Tw T;
    make_tw(T, t);
    const int r5 = __brev(t) >> 27;
    const int tP = (t == 0) ? 0 : (int)(__brev((unsigned)(32 - r5)) >> 27);

    const float4* xs = (const float4*)(x + (size_t)s * (NSIDE * NSIDE));

    // ---- row phase: 4 iterations x 2 packed real-row pairs (NF=2) ----
#pragma unroll 1
    for (int it = 0; it < 4; ++it) {
        int pr0 = it * 16 + u;
        int pr1 = pr0 + 8;
        float vr[2][4], vi[2][4];
        {
            float4 a = xs[(2 * pr0) * 32 + t];
            float4 b = xs[(2 * pr0 + 1) * 32 + t];
            vr[0][0] = a.x; vr[0][1] = a.y; vr[0][2] = a.z; vr[0][3] = a.w;
            vi[0][0] = b.x; vi[0][1] = b.y; vi[0][2] = b.z; vi[0][3] = b.w;
            float4 c = xs[(2 * pr1) * 32 + t];
            float4 d = xs[(2 * pr1 + 1) * 32 + t];
            vr[1][0] = c.x; vr[1][1] = c.y; vr[1][2] = c.z; vr[1][3] = c.w;
            vi[1][0] = d.x; vi[1][1] = d.y; vi[1][2] = d.z; vi[1][3] = d.w;
        }
        fft_fwd_n<2>(vr, vi, T, t);

#pragma unroll
        for (int f = 0; f < 2; ++f) {
            int m1 = 2 * (f == 0 ? pr0 : pr1);
            int m2 = m1 + 1;
            int C  = (m1 >> 2) & 31;
            float Znr[4], Zni[4];
#pragma unroll
            for (int k1 = 0; k1 < 4; ++k1) {
                Znr[k1] = __shfl_sync(0xffffffffu, vr[f][3 - k1], tP);
                Zni[k1] = __shfl_sync(0xffffffffu, vi[f][3 - k1], tP);
            }
            if (t == 0) {
                Znr[0] = vr[f][0]; Zni[0] = vi[f][0];
                Znr[1] = vr[f][3]; Zni[1] = vi[f][3];
                Znr[2] = vr[f][2]; Zni[2] = vi[f][2];
                Znr[3] = vr[f][1]; Zni[3] = vi[f][1];
            }
#pragma unroll
            for (int k1 = 0; k1 < 2; ++k1) {
                float Far = 0.5f * (vr[f][k1] + Znr[k1]);
                float Fai = 0.5f * (vi[f][k1] - Zni[k1]);
                float Fbr = 0.5f * (vi[f][k1] + Zni[k1]);
                float Fbi = 0.5f * (Znr[k1] - vr[f][k1]);
                int col = (t + (k1 << 5)) ^ C;
                F[(m1 << 6) + col] = make_float2(Far, Fai);
                F[(m2 << 6) + col] = make_float2(Fbr, Fbi);
            }
            if (t == 0) {
                Ny[m1] = make_float2(0.5f * (vr[f][2] + Znr[2]),
                                     0.5f * (vi[f][2] - Zni[2]));
                Ny[m2] = make_float2(0.5f * (vi[f][2] + Zni[2]),
                                     0.5f * (Znr[2] - vr[f][2]));
            }
        }
    }
    __syncthreads();

    const float scale = 1.0f / 16384.0f;

    // ---- column phase: 8 iterations, 1 unit per warp, NF=4 inverse ----
#pragma unroll 1
    for (int it = 0; it < 8; ++it) {
        int u_id = it * 8 + u;
        float gr[4][4], gi[4][4];
        int qsP, qsM;
        float msgn;

        if (u_id < 63) {
            int kq = u_id + 1;
            qsP = st_of_kq(kq);
            qsM = st_of_kq(128 - kq);
            msgn = -1.0f;

            float fvr[1][4], fvi[1][4];
#pragma unroll
            for (int j = 0; j < 4; ++j) {
                int p = 4 * t + j;
                float2 v = F[(p << 6) + (qsP ^ t)];
                fvr[0][j] = v.x;
                fvi[0][j] = v.y;
            }
            fft_fwd_n<1>(fvr, fvi, T, t);

            float kqs = (float)kq * scale;
#pragma unroll
            for (int k1 = 0; k1 < 4; ++k1) {
                int p_idx = r5 + (k1 << 5);
                float kp  = (p_idx < 64) ? (float)p_idx : (float)(p_idx - 128);
                float sgnM = (p_idx == 64) ? -1.0f : 1.0f;
                float kps = kp * scale;
                float Fr = fvr[0][k1], Fi = fvi[0][k1];
                float a = kqs * Fr, b = kps * Fi, c = kps * Fr, d = kqs * Fi;
                gr[0][k1] = -a - b;        gi[0][k1] = c - d;        // G1(+kq)
                gr[1][k1] =  a - sgnM * b; gi[1][k1] = sgnM * c + d; // G1(-kq)
                float A = ((float)kq * (float)kq - kp * kp) * scale;
                float B = 2.0f * kp * kqs;
                float Bm = sgnM * B;
                gr[2][k1] = fmaf(A, Fr,  B * Fi);                    // G2(+kq)
                gi[2][k1] = fmaf(A, Fi, -B * Fr);
                gr[3][k1] = fmaf(A, Fr, -Bm * Fi);                   // G2(-kq)
                gi[3][k1] = fmaf(A, Fi,  Bm * Fr);
            }
        } else {
            // special unit: spectral columns 0 and 64
            qsP = 0; qsM = 64;
            msgn = 1.0f;

            float fvr[2][4], fvi[2][4];
#pragma unroll
            for (int j = 0; j < 4; ++j) {
                int p = 4 * t + j;
                float2 v0 = F[(p << 6) + t];
                fvr[0][j] = v0.x;
                fvi[0][j] = v0.y;
                float2 v1 = Ny[p];
                fvr[1][j] = v1.x;
                fvi[1][j] = v1.y;
            }
            fft_fwd_n<2>(fvr, fvi, T, t);

#pragma unroll
            for (int k1 = 0; k1 < 4; ++k1) {
                int p_idx = r5 + (k1 << 5);
                float kp  = (p_idx < 64) ? (float)p_idx : (float)(p_idx - 128);
                float kps = kp * scale;
                // Y1 col 0
                gr[0][k1] = -fvi[0][k1] * kps;
                gi[0][k1] =  fvr[0][k1] * kps;
                // Y1 col 64
                float w1r = 64.0f * scale;
                gr[1][k1] = fvr[1][k1] * w1r - fvi[1][k1] * kps;
                gi[1][k1] = fvr[1][k1] * kps + fvi[1][k1] * w1r;
                // Y2 col 0
                float A0 = -kp * kps;
                gr[2][k1] = A0 * fvr[0][k1];
                gi[2][k1] = A0 * fvi[0][k1];
                // Y2 col 64
                float A4 = (4096.0f - kp * kp) * scale;
                float B4 = 128.0f * kps;
                gr[3][k1] = A4 * fvr[1][k1] - B4 * fvi[1][k1];
                gi[3][k1] = A4 * fvi[1][k1] + B4 * fvr[1][k1];
            }
        }

        fft_inv_n<4>(gr, gi, T, t);

        float4* y;
        y = (float4*)(g_Y1 + ((size_t)s * NSIDE + qsP) * NSIDE + 4 * t);
        y[0] = make_float4(gr[0][0], gi[0][0], gr[0][1], gi[0][1]);
        y[1] = make_float4(gr[0][2], gi[0][2], gr[0][3], gi[0][3]);
        y = (float4*)(g_Y1 + ((size_t)s * NSIDE + qsM) * NSIDE + 4 * t);
        y[0] = make_float4(gr[1][0], msgn * gi[1][0], gr[1][1], msgn * gi[1][1]);
        y[1] = make_float4(gr[1][2], msgn * gi[1][2], gr[1][3], msgn * gi[1][3]);
        y = (float4*)(g_Y2 + ((size_t)s * NSIDE + qsP) * NSIDE + 4 * t);
        y[0] = make_float4(gr[2][0], gi[2][0], gr[2][1], gi[2][1]);
        y[1] = make_float4(gr[2][2], gi[2][2], gr[2][3], gi[2][3]);
        y = (float4*)(g_Y2 + ((size_t)s * NSIDE + qsM) * NSIDE + 4 * t);
        y[0] = make_float4(gr[3][0], msgn * gi[3][0], gr[3][1], msgn * gi[3][1]);
        y[1] = make_float4(gr[3][2], msgn * gi[3][2], gr[3][3], msgn * gi[3][3]);
    }
}

// ---------------------------------------------------------------------------
// P2: R11 config (forward slice order) + PDL: prologue overlaps p1's tail,
// cudaGridDependencySynchronize() before any g_Y read.
// ---------------------------------------------------------------------------
__global__ void __launch_bounds__(512, 2) p2_kernel(float* __restrict__ out,
                                                    const float* __restrict__ df,
                                                    const float* __restrict__ d2f)
{
    extern __shared__ float2 smc[];
    float2* T1 = smc;            // 128*33 float2
    float2* T2 = smc + 4224;

    const int s    = blockIdx.x;
    const int m0   = blockIdx.y * 32;
    const int tid  = threadIdx.x;
    const int u    = tid >> 5;
    const int t    = tid & 31;

    Tw T;
    make_tw(T, t);

    // per-channel params (no dependence on p1 output)
    const int c = s & 63;
    float df0 = df[2 * c], df1 = df[2 * c + 1];
    float ed  = expf(df0);
    float dfcr = ed * cosf(df1), dfci = ed * sinf(df1);
    float d20 = d2f[2 * c], d21 = d2f[2 * c + 1];
    float inv_nf = 0.5f / (dfcr * dfcr + dfci * dfci);
    float hrr = (d20 * dfcr + d21 * dfci) * inv_nf;
    float hri = (d21 * dfcr - d20 * dfci) * inv_nf;

    // PDL: wait for p1 completion before touching g_Y
    cudaGridDependencySynchronize();

    const float4* y1v = (const float4*)(g_Y1 + (size_t)s * (NSIDE * NSIDE));
    const float4* y2v = (const float4*)(g_Y2 + (size_t)s * (NSIDE * NSIDE));
    const int mb = blockIdx.y * 16;

#pragma unroll
    for (int i = 0; i < 4; ++i) {
        int e  = i * 512 + tid;
        int q  = e >> 4;
        int mp = e & 15;
        float4 v1 = y1v[q * 64 + mb + mp];
        T1[q * 33 + 2 * mp]     = make_float2(v1.x, v1.y);
        T1[q * 33 + 2 * mp + 1] = make_float2(v1.z, v1.w);
        float4 v2 = y2v[q * 64 + mb + mp];
        T2[q * 33 + 2 * mp]     = make_float2(v2.x, v2.y);
        T2[q * 33 + 2 * mp + 1] = make_float2(v2.z, v2.w);
    }
    __syncthreads();

    const float EPS2   = 1e-6f;
    const float LN_EPS = -6.9077552790f;
    const float TR_MIN = -2.5902671570f;

#pragma unroll 1
    for (int iter = 0; iter < 2; ++iter) {
        int mm = iter * 16 + u;
        int m  = m0 + mm;

        float vr[2][4], vi[2][4];
#pragma unroll
        for (int k1 = 0; k1 < 4; ++k1) {
            int qs = t + (k1 << 5);
            float2 a = T1[qs * 33 + mm];
            vr[0][k1] = a.x;
            vi[0][k1] = a.y;
            float2 b = T2[qs * 33 + mm];
            vr[1][k1] = b.x;
            vi[1][k1] = b.y;
        }
        fft_inv_n<2>(vr, vi, T, t);

        float oh[4], oa[4], op[4], ot[4], os[4];
#pragma unroll
        for (int j = 0; j < 4; ++j) {
            float Dr0 = vr[0][j], Di0 = vi[0][j];
            float d2r = vr[1][j], d2i = vi[1][j];

            float h = Dr0 * Dr0 + Di0 * Di0;
            bool valid = (h >= EPS2);
            float Dr = valid ? Dr0 : 1.0f;
            float Di = valid ? Di0 : 0.0f;
            float nD = valid ? h : 1.0f;

            float lnA = 0.0f, Phi = 0.0f;
            if (valid) {
                float la = df0 - 0.5f * __logf(h);
                lnA = fminf(3.0f, fmaxf(-3.0f, la));
                float a2r = dfcr * Dr + dfci * Di;
                float a2i = dfci * Dr - dfcr * Di;
                Phi = fatan2f(a2i, a2r);
            }

            float t1r = d2r * dfcr - d2i * dfci;
            float t1i = d2r * dfci + d2i * dfcr;
            float D2r = Dr * Dr - Di * Di;
            float D2i = 2.0f * Dr * Di;
            float inv2h = 0.5f * __fdividef(1.0f, nD * nD);
            float anr = (t1r * D2r + t1i * D2i) * inv2h - hrr;
            float ani = (t1i * D2r - t1r * D2i) * inv2h - hri;

            float na = anr * anr + ani * ani;
            bool tm = valid && (na >= EPS2);
            float lnT = LN_EPS, Psi = 0.0f;
            if (tm) {
                float lt = 0.5f * __logf(na);
                lnT = fminf(3.0f, fmaxf(TR_MIN, lt));
                Psi = fatan2f(ani, anr);
            }

            oh[j] = h; oa[j] = lnA; op[j] = Phi; ot[j] = lnT; os[j] = Psi;
        }

        size_t base = (size_t)s * 16384 + (size_t)m * 128;
        ((float4*)(out + base))[t]             = *(float4*)oh;
        ((float4*)(out + PLANE + base))[t]     = *(float4*)oa;
        ((float4*)(out + 2 * PLANE + base))[t] = *(float4*)op;
        ((float4*)(out + 3 * PLANE + base))[t] = *(float4*)ot;
        ((float4*)(out + 4 * PLANE + base))[t] = *(float4*)os;
    }
}

extern "C" void kernel_launch(void* const* d_in, const int* in_sizes, int n_in,
                              void* d_out, int out_size)
{
    const float* x   = (const float*)d_in[0];
    const float* df  = (const float*)d_in[1];
    const float* d2f = (const float*)d_in[2];
    float* out = (float*)d_out;

    const int P1_SMEM = (128 * 64 + 128) * 8;   // 66560 B
    const int P2_SMEM = 2 * 4224 * 8;           // 67584 B

    cudaFuncSetAttribute(p1_kernel, cudaFuncAttributeMaxDynamicSharedMemorySize, P1_SMEM);
    cudaFuncSetAttribute(p2_kernel, cudaFuncAttributeMaxDynamicSharedMemorySize, P2_SMEM);

    p1_kernel<<<SLICES, 256, P1_SMEM>>>(x);

    // p2 with programmatic dependent launch: prologue overlaps p1 tail
    cudaLaunchConfig_t cfg = {};
    cfg.gridDim  = dim3(SLICES, 4, 1);
    cfg.blockDim = dim3(512, 1, 1);
    cfg.dynamicSmemBytes = P2_SMEM;
    cudaLaunchAttribute attrs[1];
    attrs[0].id = cudaLaunchAttributeProgrammaticStreamSerialization;
    attrs[0].val.programmaticStreamSerializationAllowed = 1;
    cfg.attrs = attrs;
    cfg.numAttrs = 1;
    cudaLaunchKernelEx(&cfg, p2_kernel, out, df, d2f);
}

// round 16
// speedup vs baseline: 1.0104x; 1.0104x over previous
#include <cuda_runtime.h>
#include <math.h>

#define NSIDE 128
#define SLICES 1024
#define PLANE 16777216ull   // 1024 * 128 * 128
#define P1_CTAS 444         // 148 SMs x 3 CTAs

__device__ float2 g_Y1[SLICES * NSIDE * NSIDE];
__device__ float2 g_Y2[SLICES * NSIDE * NSIDE];
__device__ int    g_tick;

// ---------------------------------------------------------------------------
// Register/shuffle 128-pt FFT, batched NF-ways: 128 = 32 lanes x 4 regs.
// ---------------------------------------------------------------------------
struct Tw {
    float w16r, w16i, w8r, w8i, w4r, w4i, w2r, w2i;
    float c1, s1, c2, s2, c3, s3;
};

__device__ __forceinline__ void stage_tw(int t, int h, float& cr, float& ci)
{
    if (t & h) {
        sincospif(-(float)(t & (h - 1)) / (float)h, &ci, &cr);
    } else { cr = 1.0f; ci = 0.0f; }
}

__device__ __forceinline__ void make_tw(Tw& T, int t)
{
    int br = __brev(t) >> 27;
    sincospif((float)br * (1.0f / 64.0f), &T.s1, &T.c1);
    sincospif((float)br * (1.0f / 32.0f), &T.s2, &T.c2);
    sincospif((float)(3 * br) * (1.0f / 64.0f), &T.s3, &T.c3);
    stage_tw(t, 16, T.w16r, T.w16i);
    stage_tw(t, 8,  T.w8r,  T.w8i);
    stage_tw(t, 4,  T.w4r,  T.w4i);
    stage_tw(t, 2,  T.w2r,  T.w2i);
}

__device__ __forceinline__ void cmulm(float& ar, float& ai, float br, float bi)
{
    float r = ar * br - ai * bi;
    ai = ar * bi + ai * br;
    ar = r;
}

template <int NF, int H>
__device__ __forceinline__ void lstage_f(float (&vr)[NF][4], float (&vi)[NF][4],
                                         float twr, float twi, int t)
{
    float e = (t & H) ? -1.0f : 1.0f;
    float pr[NF][4], pi[NF][4];
#pragma unroll
    for (int f = 0; f < NF; ++f)
#pragma unroll
        for (int r = 0; r < 4; ++r) {
            pr[f][r] = __shfl_xor_sync(0xffffffffu, vr[f][r], H);
            pi[f][r] = __shfl_xor_sync(0xffffffffu, vi[f][r], H);
        }
#pragma unroll
    for (int f = 0; f < NF; ++f)
#pragma unroll
        for (int r = 0; r < 4; ++r) {
            float ur = fmaf(e, vr[f][r], pr[f][r]);
            float ui = fmaf(e, vi[f][r], pi[f][r]);
            vr[f][r] = ur * twr - ui * twi;
            vi[f][r] = fmaf(ur, twi, ui * twr);
        }
}

template <int NF>
__device__ __forceinline__ void lstage_f1(float (&vr)[NF][4], float (&vi)[NF][4], int t)
{
    float e = (t & 1) ? -1.0f : 1.0f;
    float pr[NF][4], pi[NF][4];
#pragma unroll
    for (int f = 0; f < NF; ++f)
#pragma unroll
        for (int r = 0; r < 4; ++r) {
            pr[f][r] = __shfl_xor_sync(0xffffffffu, vr[f][r], 1);
            pi[f][r] = __shfl_xor_sync(0xffffffffu, vi[f][r], 1);
        }
#pragma unroll
    for (int f = 0; f < NF; ++f)
#pragma unroll
        for (int r = 0; r < 4; ++r) {
            vr[f][r] = fmaf(e, vr[f][r], pr[f][r]);
            vi[f][r] = fmaf(e, vi[f][r], pi[f][r]);
        }
}

template <int NF, int H>
__device__ __forceinline__ void lstage_i(float (&vr)[NF][4], float (&vi)[NF][4],
                                         float twr, float twi, int t)
{
    float e = (t & H) ? -1.0f : 1.0f;
    float ar[NF][4], ai[NF][4], pr[NF][4], pi[NF][4];
#pragma unroll
    for (int f = 0; f < NF; ++f)
#pragma unroll
        for (int r = 0; r < 4; ++r) {
            ar[f][r] = fmaf(vi[f][r], twi, vr[f][r] * twr);
            ai[f][r] = vi[f][r] * twr - vr[f][r] * twi;
        }
#pragma unroll
    for (int f = 0; f < NF; ++f)
#pragma unroll
        for (int r = 0; r < 4; ++r) {
            pr[f][r] = __shfl_xor_sync(0xffffffffu, ar[f][r], H);
            pi[f][r] = __shfl_xor_sync(0xffffffffu, ai[f][r], H);
        }
#pragma unroll
    for (int f = 0; f < NF; ++f)
#pragma unroll
        for (int r = 0; r < 4; ++r) {
            vr[f][r] = fmaf(e, ar[f][r], pr[f][r]);
            vi[f][r] = fmaf(e, ai[f][r], pi[f][r]);
        }
}

template <int NF>
__device__ __forceinline__ void lstage_i1(float (&vr)[NF][4], float (&vi)[NF][4], int t)
{
    float e = (t & 1) ? -1.0f : 1.0f;
    float pr[NF][4], pi[NF][4];
#pragma unroll
    for (int f = 0; f < NF; ++f)
#pragma unroll
        for (int r = 0; r < 4; ++r) {
            pr[f][r] = __shfl_xor_sync(0xffffffffu, vr[f][r], 1);
            pi[f][r] = __shfl_xor_sync(0xffffffffu, vi[f][r], 1);
        }
#pragma unroll
    for (int f = 0; f < NF; ++f)
#pragma unroll
        for (int r = 0; r < 4; ++r) {
            vr[f][r] = fmaf(e, vr[f][r], pr[f][r]);
            vi[f][r] = fmaf(e, vi[f][r], pi[f][r]);
        }
}

template <int NF>
__device__ __forceinline__ void fft_fwd_n(float (&vr)[NF][4], float (&vi)[NF][4],
                                          const Tw& T, int t)
{
    lstage_f<NF, 16>(vr, vi, T.w16r, T.w16i, t);
    lstage_f<NF, 8>(vr, vi, T.w8r, T.w8i, t);
    lstage_f<NF, 4>(vr, vi, T.w4r, T.w4i, t);
    lstage_f<NF, 2>(vr, vi, T.w2r, T.w2i, t);
    lstage_f1<NF>(vr, vi, t);
#pragma unroll
    for (int f = 0; f < NF; ++f) {
        cmulm(vr[f][1], vi[f][1], T.c1, -T.s1);
        cmulm(vr[f][2], vi[f][2], T.c2, -T.s2);
        cmulm(vr[f][3], vi[f][3], T.c3, -T.s3);
        float s02r = vr[f][0] + vr[f][2], s02i = vi[f][0] + vi[f][2];
        float d02r = vr[f][0] - vr[f][2], d02i = vi[f][0] - vi[f][2];
        float s13r = vr[f][1] + vr[f][3], s13i = vi[f][1] + vi[f][3];
        float d13r = vr[f][1] - vr[f][3], d13i = vi[f][1] - vi[f][3];
        vr[f][0] = s02r + s13r; vi[f][0] = s02i + s13i;
        vr[f][2] = s02r - s13r; vi[f][2] = s02i - s13i;
        vr[f][1] = d02r + d13i; vi[f][1] = d02i - d13r;
        vr[f][3] = d02r - d13i; vi[f][3] = d02i + d13r;
    }
}

template <int NF>
__device__ __forceinline__ void fft_inv_n(float (&vr)[NF][4], float (&vi)[NF][4],
                                          const Tw& T, int t)
{
#pragma unroll
    for (int f = 0; f < NF; ++f) {
        float s02r = vr[f][0] + vr[f][2], s02i = vi[f][0] + vi[f][2];
        float d02r = vr[f][0] - vr[f][2], d02i = vi[f][0] - vi[f][2];
        float s13r = vr[f][1] + vr[f][3], s13i = vi[f][1] + vi[f][3];
        float d13r = vr[f][1] - vr[f][3], d13i = vi[f][1] - vi[f][3];
        vr[f][0] = s02r + s13r; vi[f][0] = s02i + s13i;
        vr[f][2] = s02r - s13r; vi[f][2] = s02i - s13i;
        vr[f][1] = d02r - d13i; vi[f][1] = d02i + d13r;
        vr[f][3] = d02r + d13i; vi[f][3] = d02i - d13r;
        cmulm(vr[f][1], vi[f][1], T.c1, T.s1);
        cmulm(vr[f][2], vi[f][2], T.c2, T.s2);
        cmulm(vr[f][3], vi[f][3], T.c3, T.s3);
    }
    lstage_i1<NF>(vr, vi, t);
    lstage_i<NF, 2>(vr, vi, T.w2r, T.w2i, t);
    lstage_i<NF, 4>(vr, vi, T.w4r, T.w4i, t);
    lstage_i<NF, 8>(vr, vi, T.w8r, T.w8i, t);
    lstage_i<NF, 16>(vr, vi, T.w16r, T.w16i, t);
}

__device__ __forceinline__ float fatan2f(float y, float x)
{
    float ax = fabsf(x), ay = fabsf(y);
    float mx = fmaxf(ax, ay), mn = fminf(ax, ay);
    float a = __fdividef(mn, mx);
    float s = a * a;
    float p = -0.0117212f;
    p = fmaf(p, s, 0.05265332f);
    p = fmaf(p, s, -0.11643287f);
    p = fmaf(p, s, 0.19354346f);
    p = fmaf(p, s, -0.33262347f);
    p = fmaf(p, s, 0.99997726f);
    float r = p * a;
    if (ay > ax) r = 1.57079632679f - r;
    if (x < 0.0f) r = 3.14159265359f - r;
    return copysignf(r, y);
}

__device__ __forceinline__ int st_of_kq(int kq)
{
    return (int)(__brev((unsigned)(kq & 31)) >> 27) + (kq & 96);
}

// ---------------------------------------------------------------------------
// p1 slice body (R11-verified, 256 threads): slice s -> g_Y1/g_Y2.
// smem: F[128*64] float2 + Ny[128] float2.
// ---------------------------------------------------------------------------
__device__ void p1_slice(int s, int tid, int u, int t, const Tw& T, int r5, int tP,
                         const float* __restrict__ x, float2* F, float2* Ny)
{
    const float4* xs = (const float4*)(x + (size_t)s * (NSIDE * NSIDE));

    // ---- row phase: 4 iterations x 2 packed real-row pairs (NF=2) ----
#pragma unroll 1
    for (int it = 0; it < 4; ++it) {
        int pr0 = it * 16 + u;
        int pr1 = pr0 + 8;
        float vr[2][4], vi[2][4];
        {
            float4 a = xs[(2 * pr0) * 32 + t];
            float4 b = xs[(2 * pr0 + 1) * 32 + t];
            vr[0][0] = a.x; vr[0][1] = a.y; vr[0][2] = a.z; vr[0][3] = a.w;
            vi[0][0] = b.x; vi[0][1] = b.y; vi[0][2] = b.z; vi[0][3] = b.w;
            float4 c = xs[(2 * pr1) * 32 + t];
            float4 d = xs[(2 * pr1 + 1) * 32 + t];
            vr[1][0] = c.x; vr[1][1] = c.y; vr[1][2] = c.z; vr[1][3] = c.w;
            vi[1][0] = d.x; vi[1][1] = d.y; vi[1][2] = d.z; vi[1][3] = d.w;
        }
        fft_fwd_n<2>(vr, vi, T, t);

#pragma unroll
        for (int f = 0; f < 2; ++f) {
            int m1 = 2 * (f == 0 ? pr0 : pr1);
            int m2 = m1 + 1;
            int C  = (m1 >> 2) & 31;
            float Znr[4], Zni[4];
#pragma unroll
            for (int k1 = 0; k1 < 4; ++k1) {
                Znr[k1] = __shfl_sync(0xffffffffu, vr[f][3 - k1], tP);
                Zni[k1] = __shfl_sync(0xffffffffu, vi[f][3 - k1], tP);
            }
            if (t == 0) {
                Znr[0] = vr[f][0]; Zni[0] = vi[f][0];
                Znr[1] = vr[f][3]; Zni[1] = vi[f][3];
                Znr[2] = vr[f][2]; Zni[2] = vi[f][2];
                Znr[3] = vr[f][1]; Zni[3] = vi[f][1];
            }
#pragma unroll
            for (int k1 = 0; k1 < 2; ++k1) {
                float Far = 0.5f * (vr[f][k1] + Znr[k1]);
                float Fai = 0.5f * (vi[f][k1] - Zni[k1]);
                float Fbr = 0.5f * (vi[f][k1] + Zni[k1]);
                float Fbi = 0.5f * (Znr[k1] - vr[f][k1]);
                int col = (t + (k1 << 5)) ^ C;
                F[(m1 << 6) + col] = make_float2(Far, Fai);
                F[(m2 << 6) + col] = make_float2(Fbr, Fbi);
            }
            if (t == 0) {
                Ny[m1] = make_float2(0.5f * (vr[f][2] + Znr[2]),
                                     0.5f * (vi[f][2] - Zni[2]));
                Ny[m2] = make_float2(0.5f * (vi[f][2] + Zni[2]),
                                     0.5f * (Znr[2] - vr[f][2]));
            }
        }
    }
    __syncthreads();

    const float scale = 1.0f / 16384.0f;

    // ---- column phase: 8 iterations, 1 unit per warp, 2x NF=2 inverse ----
#pragma unroll 1
    for (int it = 0; it < 8; ++it) {
        int u_id = it * 8 + u;

        if (u_id < 63) {
            int kq = u_id + 1;
            int qsP = st_of_kq(kq);
            int qsM = st_of_kq(128 - kq);

            float fvr[1][4], fvi[1][4];
#pragma unroll
            for (int j = 0; j < 4; ++j) {
                int p = 4 * t + j;
                float2 v = F[(p << 6) + (qsP ^ t)];
                fvr[0][j] = v.x;
                fvi[0][j] = v.y;
            }
            fft_fwd_n<1>(fvr, fvi, T, t);

            float kqs = (float)kq * scale;

            float gr[2][4], gi[2][4];
#pragma unroll
            for (int k1 = 0; k1 < 4; ++k1) {
                int p_idx = r5 + (k1 << 5);
                float kp  = (p_idx < 64) ? (float)p_idx : (float)(p_idx - 128);
                float sgnM = (p_idx == 64) ? -1.0f : 1.0f;
                float kps = kp * scale;
                float Fr = fvr[0][k1], Fi = fvi[0][k1];
                float a = kqs * Fr, b = kps * Fi, c = kps * Fr, d = kqs * Fi;
                gr[0][k1] = -a - b;        gi[0][k1] = c - d;
                gr[1][k1] =  a - sgnM * b; gi[1][k1] = sgnM * c + d;
            }
            fft_inv_n<2>(gr, gi, T, t);
            {
                float4* y;
                y = (float4*)(g_Y1 + ((size_t)s * NSIDE + qsP) * NSIDE + 4 * t);
                y[0] = make_float4(gr[0][0], gi[0][0], gr[0][1], gi[0][1]);
                y[1] = make_float4(gr[0][2], gi[0][2], gr[0][3], gi[0][3]);
                y = (float4*)(g_Y1 + ((size_t)s * NSIDE + qsM) * NSIDE + 4 * t);
                y[0] = make_float4(gr[1][0], -gi[1][0], gr[1][1], -gi[1][1]);
                y[1] = make_float4(gr[1][2], -gi[1][2], gr[1][3], -gi[1][3]);
            }

#pragma unroll
            for (int k1 = 0; k1 < 4; ++k1) {
                int p_idx = r5 + (k1 << 5);
                float kp  = (p_idx < 64) ? (float)p_idx : (float)(p_idx - 128);
                float sgnM = (p_idx == 64) ? -1.0f : 1.0f;
                float Fr = fvr[0][k1], Fi = fvi[0][k1];
                float A = ((float)kq * (float)kq - kp * kp) * scale;
                float B = 2.0f * kp * kqs;
                float Bm = sgnM * B;
                gr[0][k1] = fmaf(A, Fr,  B * Fi);
                gi[0][k1] = fmaf(A, Fi, -B * Fr);
                gr[1][k1] = fmaf(A, Fr, -Bm * Fi);
                gi[1][k1] = fmaf(A, Fi,  Bm * Fr);
            }
            fft_inv_n<2>(gr, gi, T, t);
            {
                float4* y;
                y = (float4*)(g_Y2 + ((size_t)s * NSIDE + qsP) * NSIDE + 4 * t);
                y[0] = make_float4(gr[0][0], gi[0][0], gr[0][1], gi[0][1]);
                y[1] = make_float4(gr[0][2], gi[0][2], gr[0][3], gi[0][3]);
                y = (float4*)(g_Y2 + ((size_t)s * NSIDE + qsM) * NSIDE + 4 * t);
                y[0] = make_float4(gr[1][0], -gi[1][0], gr[1][1], -gi[1][1]);
                y[1] = make_float4(gr[1][2], -gi[1][2], gr[1][3], -gi[1][3]);
            }
        } else if (u_id == 63) {
            float fvr[2][4], fvi[2][4];
#pragma unroll
            for (int j = 0; j < 4; ++j) {
                int p = 4 * t + j;
                float2 v0 = F[(p << 6) + t];
                fvr[0][j] = v0.x;
                fvi[0][j] = v0.y;
                float2 v1 = Ny[p];
                fvr[1][j] = v1.x;
                fvi[1][j] = v1.y;
            }
            fft_fwd_n<2>(fvr, fvi, T, t);

            float gr[2][4], gi[2][4];
#pragma unroll
            for (int k1 = 0; k1 < 4; ++k1) {
                int p_idx = r5 + (k1 << 5);
                float kp  = (p_idx < 64) ? (float)p_idx : (float)(p_idx - 128);
                float kps = kp * scale;
                gr[0][k1] = -fvi[0][k1] * kps;
                gi[0][k1] =  fvr[0][k1] * kps;
                float w1r = 64.0f * scale;
                gr[1][k1] = fvr[1][k1] * w1r - fvi[1][k1] * kps;
                gi[1][k1] = fvr[1][k1] * kps + fvi[1][k1] * w1r;
            }
            fft_inv_n<2>(gr, gi, T, t);
            {
                float4* y;
                y = (float4*)(g_Y1 + ((size_t)s * NSIDE + 0) * NSIDE + 4 * t);
                y[0] = make_float4(gr[0][0], gi[0][0], gr[0][1], gi[0][1]);
                y[1] = make_float4(gr[0][2], gi[0][2], gr[0][3], gi[0][3]);
                y = (float4*)(g_Y1 + ((size_t)s * NSIDE + 64) * NSIDE + 4 * t);
                y[0] = make_float4(gr[1][0], gi[1][0], gr[1][1], gi[1][1]);
                y[1] = make_float4(gr[1][2], gi[1][2], gr[1][3], gi[1][3]);
            }

#pragma unroll
            for (int k1 = 0; k1 < 4; ++k1) {
                int p_idx = r5 + (k1 << 5);
                float kp  = (p_idx < 64) ? (float)p_idx : (float)(p_idx - 128);
                float kps = kp * scale;
                float A0 = -kp * kps;
                gr[0][k1] = A0 * fvr[0][k1];
                gi[0][k1] = A0 * fvi[0][k1];
                float A4 = (4096.0f - kp * kp) * scale;
                float B4 = 128.0f * kps;
                gr[1][k1] = A4 * fvr[1][k1] - B4 * fvi[1][k1];
                gi[1][k1] = A4 * fvi[1][k1] + B4 * fvr[1][k1];
            }
            fft_inv_n<2>(gr, gi, T, t);
            {
                float4* y;
                y = (float4*)(g_Y2 + ((size_t)s * NSIDE + 0) * NSIDE + 4 * t);
                y[0] = make_float4(gr[0][0], gi[0][0], gr[0][1], gi[0][1]);
                y[1] = make_float4(gr[0][2], gi[0][2], gr[0][3], gi[0][3]);
                y = (float4*)(g_Y2 + ((size_t)s * NSIDE + 64) * NSIDE + 4 * t);
                y[0] = make_float4(gr[1][0], gi[1][0], gr[1][1], gi[1][1]);
                y[1] = make_float4(gr[1][2], gi[1][2], gr[1][3], gi[1][3]);
            }
        }
    }
}

// ---------------------------------------------------------------------------
// P1: persistent producer kernel. 444 CTAs x 256 threads, 3 CTAs/SM.
// Slices pulled from a global atomic ticket (producers only -> no convoy).
// ---------------------------------------------------------------------------
__global__ void __launch_bounds__(256, 3) p1_kernel(const float* __restrict__ x)
{
    extern __shared__ float2 smc[];
    float2* F  = smc;           // 128*64 float2
    float2* Ny = smc + 8192;    // 128 float2
    __shared__ int sh_s;

    const int tid = threadIdx.x;
    const int u   = tid >> 5;   // 0..7
    const int t   = tid & 31;

    Tw T;
    make_tw(T, t);
    const int r5 = __brev(t) >> 27;
    const int tP = (t == 0) ? 0 : (int)(__brev((unsigned)(32 - r5)) >> 27);

    while (true) {
        if (tid == 0) sh_s = atomicAdd(&g_tick, 1);
        __syncthreads();
        int s = sh_s;
        __syncthreads();            // sh_s consumed; also fences smem reuse
        if (s >= SLICES) break;
        p1_slice(s, tid, u, t, T, r5, tP, x, F, Ny);
        __syncthreads();            // column-phase reads done before next row-phase writes
    }
}

// ---------------------------------------------------------------------------
// P2: R11 verbatim. Interleaved float2 tiles, NF=2 inverse, fast epilogue.
// ---------------------------------------------------------------------------
__global__ void __launch_bounds__(512, 2) p2_kernel(float* __restrict__ out,
                                                    const float* __restrict__ df,
                                                    const float* __restrict__ d2f)
{
    extern __shared__ float2 smc[];
    float2* T1 = smc;            // 128*33 float2
    float2* T2 = smc + 4224;

    const int s    = blockIdx.x;
    const int m0   = blockIdx.y * 32;
    const int tid  = threadIdx.x;
    const int u    = tid >> 5;
    const int t    = tid & 31;

    Tw T;
    make_tw(T, t);

    const float4* y1v = (const float4*)(g_Y1 + (size_t)s * (NSIDE * NSIDE));
    const float4* y2v = (const float4*)(g_Y2 + (size_t)s * (NSIDE * NSIDE));
    const int mb = blockIdx.y * 16;

#pragma unroll
    for (int i = 0; i < 4; ++i) {
        int e  = i * 512 + tid;
        int q  = e >> 4;
        int mp = e & 15;
        float4 v1 = y1v[q * 64 + mb + mp];
        T1[q * 33 + 2 * mp]     = make_float2(v1.x, v1.y);
        T1[q * 33 + 2 * mp + 1] = make_float2(v1.z, v1.w);
        float4 v2 = y2v[q * 64 + mb + mp];
        T2[q * 33 + 2 * mp]     = make_float2(v2.x, v2.y);
        T2[q * 33 + 2 * mp + 1] = make_float2(v2.z, v2.w);
    }
    __syncthreads();

    const int c = s & 63;
    float df0 = df[2 * c], df1 = df[2 * c + 1];
    float ed  = expf(df0);
    float dfcr = ed * cosf(df1), dfci = ed * sinf(df1);
    float d20 = d2f[2 * c], d21 = d2f[2 * c + 1];
    float inv_nf = 0.5f / (dfcr * dfcr + dfci * dfci);
    float hrr = (d20 * dfcr + d21 * dfci) * inv_nf;
    float hri = (d21 * dfcr - d20 * dfci) * inv_nf;

    const float EPS2   = 1e-6f;
    const float LN_EPS = -6.9077552790f;
    const float TR_MIN = -2.5902671570f;

#pragma unroll 1
    for (int iter = 0; iter < 2; ++iter) {
        int mm = iter * 16 + u;
        int m  = m0 + mm;

        float vr[2][4], vi[2][4];
#pragma unroll
        for (int k1 = 0; k1 < 4; ++k1) {
            int qs = t + (k1 << 5);
            float2 a = T1[qs * 33 + mm];
            vr[0][k1] = a.x;
            vi[0][k1] = a.y;
            float2 b = T2[qs * 33 + mm];
            vr[1][k1] = b.x;
            vi[1][k1] = b.y;
        }
        fft_inv_n<2>(vr, vi, T, t);

        float oh[4], oa[4], op[4], ot[4], os[4];
#pragma unroll
        for (int j = 0; j < 4; ++j) {
            float Dr0 = vr[0][j], Di0 = vi[0][j];
            float d2r = vr[1][j], d2i = vi[1][j];

            float h = Dr0 * Dr0 + Di0 * Di0;
            bool valid = (h >= EPS2);
            float Dr = valid ? Dr0 : 1.0f;
            float Di = valid ? Di0 : 0.0f;
            float nD = valid ? h : 1.0f;

            float lnA = 0.0f, Phi = 0.0f;
            if (valid) {
                float la = df0 - 0.5f * __logf(h);
                lnA = fminf(3.0f, fmaxf(-3.0f, la));
                float a2r = dfcr * Dr + dfci * Di;
                float a2i = dfci * Dr - dfcr * Di;
                Phi = fatan2f(a2i, a2r);
            }

            float t1r = d2r * dfcr - d2i * dfci;
            float t1i = d2r * dfci + d2i * dfcr;
            float D2r = Dr * Dr - Di * Di;
            float D2i = 2.0f * Dr * Di;
            float inv2h = 0.5f * __fdividef(1.0f, nD * nD);
            float anr = (t1r * D2r + t1i * D2i) * inv2h - hrr;
            float ani = (t1i * D2r - t1r * D2i) * inv2h - hri;

            float na = anr * anr + ani * ani;
            bool tm = valid && (na >= EPS2);
            float lnT = LN_EPS, Psi = 0.0f;
            if (tm) {
                float lt = 0.5f * __logf(na);
                lnT = fminf(3.0f, fmaxf(TR_MIN, lt));
                Psi = fatan2f(ani, anr);
            }

            oh[j] = h; oa[j] = lnA; op[j] = Phi; ot[j] = lnT; os[j] = Psi;
        }

        size_t base = (size_t)s * 16384 + (size_t)m * 128;
        ((float4*)(out + base))[t]             = *(float4*)oh;
        ((float4*)(out + PLANE + base))[t]     = *(float4*)oa;
        ((float4*)(out + 2 * PLANE + base))[t] = *(float4*)op;
        ((float4*)(out + 3 * PLANE + base))[t] = *(float4*)ot;
        ((float4*)(out + 4 * PLANE + base))[t] = *(float4*)os;
    }
}

extern "C" void kernel_launch(void* const* d_in, const int* in_sizes, int n_in,
                              void* d_out, int out_size)
{
    const float* x   = (const float*)d_in[0];
    const float* df  = (const float*)d_in[1];
    const float* d2f = (const float*)d_in[2];
    float* out = (float*)d_out;

    const int P1_SMEM = (128 * 64 + 128) * 8;   // 66560 B
    const int P2_SMEM = 2 * 4224 * 8;           // 67584 B

    cudaFuncSetAttribute(p1_kernel, cudaFuncAttributeMaxDynamicSharedMemorySize, P1_SMEM);
    cudaFuncSetAttribute(p2_kernel, cudaFuncAttributeMaxDynamicSharedMemorySize, P2_SMEM);

    void* tkp = nullptr;
    cudaGetSymbolAddress(&tkp, g_tick);
    cudaMemsetAsync(tkp, 0, sizeof(int));

    p1_kernel<<<P1_CTAS, 256, P1_SMEM>>>(x);
    p2_kernel<<<dim3(SLICES, 4), 512, P2_SMEM>>>(out, df, d2f);
}

// round 17
// speedup vs baseline: 1.0648x; 1.0538x over previous
#include <cuda_runtime.h>
#include <math.h>

#define NSIDE 128
#define SLICES 1024
#define PLANE 16777216ull   // 1024 * 128 * 128

__device__ float2 g_Y1[SLICES * NSIDE * NSIDE];
__device__ float2 g_Y2[SLICES * NSIDE * NSIDE];

// ---------------------------------------------------------------------------
// Register/shuffle 128-pt FFT, batched NF-ways: 128 = 32 lanes x 4 regs.
// Input layout (P4):  thread t holds x[4t + j], j = reg 0..3
// Output layout (SP): thread b, reg k1 holds X[bitrev5(b) + 32*k1]
// Inverse consumes SP, produces P4, UNSCALED (x128).
// ---------------------------------------------------------------------------
struct Tw {
    float w16r, w16i, w8r, w8i, w4r, w4i, w2r, w2i;
    float c1, s1, c2, s2, c3, s3;
};

__device__ __forceinline__ void stage_tw(int t, int h, float& cr, float& ci)
{
    if (t & h) {
        sincospif(-(float)(t & (h - 1)) / (float)h, &ci, &cr);
    } else { cr = 1.0f; ci = 0.0f; }
}

__device__ __forceinline__ void make_tw(Tw& T, int t)
{
    int br = __brev(t) >> 27;
    sincospif((float)br * (1.0f / 64.0f), &T.s1, &T.c1);
    sincospif((float)br * (1.0f / 32.0f), &T.s2, &T.c2);
    sincospif((float)(3 * br) * (1.0f / 64.0f), &T.s3, &T.c3);
    stage_tw(t, 16, T.w16r, T.w16i);
    stage_tw(t, 8,  T.w8r,  T.w8i);
    stage_tw(t, 4,  T.w4r,  T.w4i);
    stage_tw(t, 2,  T.w2r,  T.w2i);
}

__device__ __forceinline__ void cmulm(float& ar, float& ai, float br, float bi)
{
    float r = ar * br - ai * bi;
    ai = ar * bi + ai * br;
    ar = r;
}

template <int NF, int H>
__device__ __forceinline__ void lstage_f(float (&vr)[NF][4], float (&vi)[NF][4],
                                         float twr, float twi, int t)
{
    float e = (t & H) ? -1.0f : 1.0f;
    float pr[NF][4], pi[NF][4];
#pragma unroll
    for (int f = 0; f < NF; ++f)
#pragma unroll
        for (int r = 0; r < 4; ++r) {
            pr[f][r] = __shfl_xor_sync(0xffffffffu, vr[f][r], H);
            pi[f][r] = __shfl_xor_sync(0xffffffffu, vi[f][r], H);
        }
#pragma unroll
    for (int f = 0; f < NF; ++f)
#pragma unroll
        for (int r = 0; r < 4; ++r) {
            float ur = fmaf(e, vr[f][r], pr[f][r]);
            float ui = fmaf(e, vi[f][r], pi[f][r]);
            vr[f][r] = ur * twr - ui * twi;
            vi[f][r] = fmaf(ur, twi, ui * twr);
        }
}

template <int NF>
__device__ __forceinline__ void lstage_f1(float (&vr)[NF][4], float (&vi)[NF][4], int t)
{
    float e = (t & 1) ? -1.0f : 1.0f;
    float pr[NF][4], pi[NF][4];
#pragma unroll
    for (int f = 0; f < NF; ++f)
#pragma unroll
        for (int r = 0; r < 4; ++r) {
            pr[f][r] = __shfl_xor_sync(0xffffffffu, vr[f][r], 1);
            pi[f][r] = __shfl_xor_sync(0xffffffffu, vi[f][r], 1);
        }
#pragma unroll
    for (int f = 0; f < NF; ++f)
#pragma unroll
        for (int r = 0; r < 4; ++r) {
            vr[f][r] = fmaf(e, vr[f][r], pr[f][r]);
            vi[f][r] = fmaf(e, vi[f][r], pi[f][r]);
        }
}

template <int NF, int H>
__device__ __forceinline__ void lstage_i(float (&vr)[NF][4], float (&vi)[NF][4],
                                         float twr, float twi, int t)
{
    float e = (t & H) ? -1.0f : 1.0f;
    float ar[NF][4], ai[NF][4], pr[NF][4], pi[NF][4];
#pragma unroll
    for (int f = 0; f < NF; ++f)
#pragma unroll
        for (int r = 0; r < 4; ++r) {
            ar[f][r] = fmaf(vi[f][r], twi, vr[f][r] * twr);
            ai[f][r] = vi[f][r] * twr - vr[f][r] * twi;
        }
#pragma unroll
    for (int f = 0; f < NF; ++f)
#pragma unroll
        for (int r = 0; r < 4; ++r) {
            pr[f][r] = __shfl_xor_sync(0xffffffffu, ar[f][r], H);
            pi[f][r] = __shfl_xor_sync(0xffffffffu, ai[f][r], H);
        }
#pragma unroll
    for (int f = 0; f < NF; ++f)
#pragma unroll
        for (int r = 0; r < 4; ++r) {
            vr[f][r] = fmaf(e, ar[f][r], pr[f][r]);
            vi[f][r] = fmaf(e, ai[f][r], pi[f][r]);
        }
}

template <int NF>
__device__ __forceinline__ void lstage_i1(float (&vr)[NF][4], float (&vi)[NF][4], int t)
{
    float e = (t & 1) ? -1.0f : 1.0f;
    float pr[NF][4], pi[NF][4];
#pragma unroll
    for (int f = 0; f < NF; ++f)
#pragma unroll
        for (int r = 0; r < 4; ++r) {
            pr[f][r] = __shfl_xor_sync(0xffffffffu, vr[f][r], 1);
            pi[f][r] = __shfl_xor_sync(0xffffffffu, vi[f][r], 1);
        }
#pragma unroll
    for (int f = 0; f < NF; ++f)
#pragma unroll
        for (int r = 0; r < 4; ++r) {
            vr[f][r] = fmaf(e, vr[f][r], pr[f][r]);
            vi[f][r] = fmaf(e, vi[f][r], pi[f][r]);
        }
}

template <int NF>
__device__ __forceinline__ void fft_fwd_n(float (&vr)[NF][4], float (&vi)[NF][4],
                                          const Tw& T, int t)
{
    lstage_f<NF, 16>(vr, vi, T.w16r, T.w16i, t);
    lstage_f<NF, 8>(vr, vi, T.w8r, T.w8i, t);
    lstage_f<NF, 4>(vr, vi, T.w4r, T.w4i, t);
    lstage_f<NF, 2>(vr, vi, T.w2r, T.w2i, t);
    lstage_f1<NF>(vr, vi, t);
#pragma unroll
    for (int f = 0; f < NF; ++f) {
        cmulm(vr[f][1], vi[f][1], T.c1, -T.s1);
        cmulm(vr[f][2], vi[f][2], T.c2, -T.s2);
        cmulm(vr[f][3], vi[f][3], T.c3, -T.s3);
        float s02r = vr[f][0] + vr[f][2], s02i = vi[f][0] + vi[f][2];
        float d02r = vr[f][0] - vr[f][2], d02i = vi[f][0] - vi[f][2];
        float s13r = vr[f][1] + vr[f][3], s13i = vi[f][1] + vi[f][3];
        float d13r = vr[f][1] - vr[f][3], d13i = vi[f][1] - vi[f][3];
        vr[f][0] = s02r + s13r; vi[f][0] = s02i + s13i;
        vr[f][2] = s02r - s13r; vi[f][2] = s02i - s13i;
        vr[f][1] = d02r + d13i; vi[f][1] = d02i - d13r;
        vr[f][3] = d02r - d13i; vi[f][3] = d02i + d13r;
    }
}

template <int NF>
__device__ __forceinline__ void fft_inv_n(float (&vr)[NF][4], float (&vi)[NF][4],
                                          const Tw& T, int t)
{
#pragma unroll
    for (int f = 0; f < NF; ++f) {
        float s02r = vr[f][0] + vr[f][2], s02i = vi[f][0] + vi[f][2];
        float d02r = vr[f][0] - vr[f][2], d02i = vi[f][0] - vi[f][2];
        float s13r = vr[f][1] + vr[f][3], s13i = vi[f][1] + vi[f][3];
        float d13r = vr[f][1] - vr[f][3], d13i = vi[f][1] - vi[f][3];
        vr[f][0] = s02r + s13r; vi[f][0] = s02i + s13i;
        vr[f][2] = s02r - s13r; vi[f][2] = s02i - s13i;
        vr[f][1] = d02r - d13i; vi[f][1] = d02i + d13r;
        vr[f][3] = d02r + d13i; vi[f][3] = d02i - d13r;
        cmulm(vr[f][1], vi[f][1], T.c1, T.s1);
        cmulm(vr[f][2], vi[f][2], T.c2, T.s2);
        cmulm(vr[f][3], vi[f][3], T.c3, T.s3);
    }
    lstage_i1<NF>(vr, vi, t);
    lstage_i<NF, 2>(vr, vi, T.w2r, T.w2i, t);
    lstage_i<NF, 4>(vr, vi, T.w4r, T.w4i, t);
    lstage_i<NF, 8>(vr, vi, T.w8r, T.w8i, t);
    lstage_i<NF, 16>(vr, vi, T.w16r, T.w16i, t);
}

__device__ __forceinline__ float fatan2f(float y, float x)
{
    float ax = fabsf(x), ay = fabsf(y);
    float mx = fmaxf(ax, ay), mn = fminf(ax, ay);
    float a = __fdividef(mn, mx);
    float s = a * a;
    float p = -0.0117212f;
    p = fmaf(p, s, 0.05265332f);
    p = fmaf(p, s, -0.11643287f);
    p = fmaf(p, s, 0.19354346f);
    p = fmaf(p, s, -0.33262347f);
    p = fmaf(p, s, 0.99997726f);
    float r = p * a;
    if (ay > ax) r = 1.57079632679f - r;
    if (x < 0.0f) r = 3.14159265359f - r;
    return copysignf(r, y);
}

__device__ __forceinline__ int st_of_kq(int kq)
{
    return (int)(__brev((unsigned)(kq & 31)) >> 27) + (kq & 96);
}

// ---------------------------------------------------------------------------
// P1: 256 threads, 3 CTAs/SM. Interleaved float2 half-spectrum smem:
// F[128][64] float2 (cols kq 0..63, swizzled) + Ny[128] float2 (col 64).
// ---------------------------------------------------------------------------
__global__ void __launch_bounds__(256, 3) p1_kernel(const float* __restrict__ x)
{
    extern __shared__ float2 smc[];
    float2* F  = smc;           // 128*64 float2, row m stride 64
    float2* Ny = smc + 8192;    // 128 float2

    const int tid = threadIdx.x;
    const int s   = blockIdx.x;
    const int u   = tid >> 5;   // 0..7
    const int t   = tid & 31;

    Tw T;
    make_tw(T, t);
    const int r5 = __brev(t) >> 27;
    const int tP = (t == 0) ? 0 : (int)(__brev((unsigned)(32 - r5)) >> 27);

    const float4* xs = (const float4*)(x + (size_t)s * (NSIDE * NSIDE));

    // ---- row phase: 4 iterations x 2 packed real-row pairs (NF=2) ----
#pragma unroll 1
    for (int it = 0; it < 4; ++it) {
        int pr0 = it * 16 + u;
        int pr1 = pr0 + 8;
        float vr[2][4], vi[2][4];
        {
            float4 a = xs[(2 * pr0) * 32 + t];
            float4 b = xs[(2 * pr0 + 1) * 32 + t];
            vr[0][0] = a.x; vr[0][1] = a.y; vr[0][2] = a.z; vr[0][3] = a.w;
            vi[0][0] = b.x; vi[0][1] = b.y; vi[0][2] = b.z; vi[0][3] = b.w;
            float4 c = xs[(2 * pr1) * 32 + t];
            float4 d = xs[(2 * pr1 + 1) * 32 + t];
            vr[1][0] = c.x; vr[1][1] = c.y; vr[1][2] = c.z; vr[1][3] = c.w;
            vi[1][0] = d.x; vi[1][1] = d.y; vi[1][2] = d.z; vi[1][3] = d.w;
        }
        fft_fwd_n<2>(vr, vi, T, t);

#pragma unroll
        for (int f = 0; f < 2; ++f) {
            int m1 = 2 * (f == 0 ? pr0 : pr1);
            int m2 = m1 + 1;
            int C  = (m1 >> 2) & 31;
            float Znr[4], Zni[4];
#pragma unroll
            for (int k1 = 0; k1 < 4; ++k1) {
                Znr[k1] = __shfl_sync(0xffffffffu, vr[f][3 - k1], tP);
                Zni[k1] = __shfl_sync(0xffffffffu, vi[f][3 - k1], tP);
            }
            if (t == 0) {
                Znr[0] = vr[f][0]; Zni[0] = vi[f][0];
                Znr[1] = vr[f][3]; Zni[1] = vi[f][3];
                Znr[2] = vr[f][2]; Zni[2] = vi[f][2];
                Znr[3] = vr[f][1]; Zni[3] = vi[f][1];
            }
#pragma unroll
            for (int k1 = 0; k1 < 2; ++k1) {
                float Far = 0.5f * (vr[f][k1] + Znr[k1]);
                float Fai = 0.5f * (vi[f][k1] - Zni[k1]);
                float Fbr = 0.5f * (vi[f][k1] + Zni[k1]);
                float Fbi = 0.5f * (Znr[k1] - vr[f][k1]);
                int col = (t + (k1 << 5)) ^ C;
                F[(m1 << 6) + col] = make_float2(Far, Fai);
                F[(m2 << 6) + col] = make_float2(Fbr, Fbi);
            }
            if (t == 0) {
                Ny[m1] = make_float2(0.5f * (vr[f][2] + Znr[2]),
                                     0.5f * (vi[f][2] - Zni[2]));
                Ny[m2] = make_float2(0.5f * (vi[f][2] + Zni[2]),
                                     0.5f * (Znr[2] - vr[f][2]));
            }
        }
    }
    __syncthreads();

    const float scale = 1.0f / 16384.0f;

    // ---- column phase: 8 iterations, 1 unit per warp ----
#pragma unroll 1
    for (int it = 0; it < 8; ++it) {
        int u_id = it * 8 + u;

        if (u_id < 63) {
            int kq = u_id + 1;
            int qsP = st_of_kq(kq);
            int qsM = st_of_kq(128 - kq);

            float fvr[1][4], fvi[1][4];
#pragma unroll
            for (int j = 0; j < 4; ++j) {
                int p = 4 * t + j;
                float2 v = F[(p << 6) + (qsP ^ t)];
                fvr[0][j] = v.x;
                fvi[0][j] = v.y;
            }
            fft_fwd_n<1>(fvr, fvi, T, t);

            float kqs = (float)kq * scale;

            float gr[2][4], gi[2][4];
#pragma unroll
            for (int k1 = 0; k1 < 4; ++k1) {
                int p_idx = r5 + (k1 << 5);
                float kp  = (p_idx < 64) ? (float)p_idx : (float)(p_idx - 128);
                float sgnM = (p_idx == 64) ? -1.0f : 1.0f;
                float kps = kp * scale;
                float Fr = fvr[0][k1], Fi = fvi[0][k1];
                float a = kqs * Fr, b = kps * Fi, c = kps * Fr, d = kqs * Fi;
                gr[0][k1] = -a - b;        gi[0][k1] = c - d;
                gr[1][k1] =  a - sgnM * b; gi[1][k1] = sgnM * c + d;
            }
            fft_inv_n<2>(gr, gi, T, t);
            {
                float4* y;
                y = (float4*)(g_Y1 + ((size_t)s * NSIDE + qsP) * NSIDE + 4 * t);
                y[0] = make_float4(gr[0][0], gi[0][0], gr[0][1], gi[0][1]);
                y[1] = make_float4(gr[0][2], gi[0][2], gr[0][3], gi[0][3]);
                y = (float4*)(g_Y1 + ((size_t)s * NSIDE + qsM) * NSIDE + 4 * t);
                y[0] = make_float4(gr[1][0], -gi[1][0], gr[1][1], -gi[1][1]);
                y[1] = make_float4(gr[1][2], -gi[1][2], gr[1][3], -gi[1][3]);
            }

#pragma unroll
            for (int k1 = 0; k1 < 4; ++k1) {
                int p_idx = r5 + (k1 << 5);
                float kp  = (p_idx < 64) ? (float)p_idx : (float)(p_idx - 128);
                float sgnM = (p_idx == 64) ? -1.0f : 1.0f;
                float Fr = fvr[0][k1], Fi = fvi[0][k1];
                float A = ((float)kq * (float)kq - kp * kp) * scale;
                float B = 2.0f * kp * kqs;
                float Bm = sgnM * B;
                gr[0][k1] = fmaf(A, Fr,  B * Fi);
                gi[0][k1] = fmaf(A, Fi, -B * Fr);
                gr[1][k1] = fmaf(A, Fr, -Bm * Fi);
                gi[1][k1] = fmaf(A, Fi,  Bm * Fr);
            }
            fft_inv_n<2>(gr, gi, T, t);
            {
                float4* y;
                y = (float4*)(g_Y2 + ((size_t)s * NSIDE + qsP) * NSIDE + 4 * t);
                y[0] = make_float4(gr[0][0], gi[0][0], gr[0][1], gi[0][1]);
                y[1] = make_float4(gr[0][2], gi[0][2], gr[0][3], gi[0][3]);
                y = (float4*)(g_Y2 + ((size_t)s * NSIDE + qsM) * NSIDE + 4 * t);
                y[0] = make_float4(gr[1][0], -gi[1][0], gr[1][1], -gi[1][1]);
                y[1] = make_float4(gr[1][2], -gi[1][2], gr[1][3], -gi[1][3]);
            }
        } else if (u_id == 63) {
            float fvr[2][4], fvi[2][4];
#pragma unroll
            for (int j = 0; j < 4; ++j) {
                int p = 4 * t + j;
                float2 v0 = F[(p << 6) + t];
                fvr[0][j] = v0.x;
                fvi[0][j] = v0.y;
                float2 v1 = Ny[p];
                fvr[1][j] = v1.x;
                fvi[1][j] = v1.y;
            }
            fft_fwd_n<2>(fvr, fvi, T, t);

            float gr[2][4], gi[2][4];
#pragma unroll
            for (int k1 = 0; k1 < 4; ++k1) {
                int p_idx = r5 + (k1 << 5);
                float kp  = (p_idx < 64) ? (float)p_idx : (float)(p_idx - 128);
                float kps = kp * scale;
                gr[0][k1] = -fvi[0][k1] * kps;
                gi[0][k1] =  fvr[0][k1] * kps;
                float w1r = 64.0f * scale;
                gr[1][k1] = fvr[1][k1] * w1r - fvi[1][k1] * kps;
                gi[1][k1] = fvr[1][k1] * kps + fvi[1][k1] * w1r;
            }
            fft_inv_n<2>(gr, gi, T, t);
            {
                float4* y;
                y = (float4*)(g_Y1 + ((size_t)s * NSIDE + 0) * NSIDE + 4 * t);
                y[0] = make_float4(gr[0][0], gi[0][0], gr[0][1], gi[0][1]);
                y[1] = make_float4(gr[0][2], gi[0][2], gr[0][3], gi[0][3]);
                y = (float4*)(g_Y1 + ((size_t)s * NSIDE + 64) * NSIDE + 4 * t);
                y[0] = make_float4(gr[1][0], gi[1][0], gr[1][1], gi[1][1]);
                y[1] = make_float4(gr[1][2], gi[1][2], gr[1][3], gi[1][3]);
            }

#pragma unroll
            for (int k1 = 0; k1 < 4; ++k1) {
                int p_idx = r5 + (k1 << 5);
                float kp  = (p_idx < 64) ? (float)p_idx : (float)(p_idx - 128);
                float kps = kp * scale;
                float A0 = -kp * kps;
                gr[0][k1] = A0 * fvr[0][k1];
                gi[0][k1] = A0 * fvi[0][k1];
                float A4 = (4096.0f - kp * kp) * scale;
                float B4 = 128.0f * kps;
                gr[1][k1] = A4 * fvr[1][k1] - B4 * fvi[1][k1];
                gi[1][k1] = A4 * fvi[1][k1] + B4 * fvr[1][k1];
            }
            fft_inv_n<2>(gr, gi, T, t);
            {
                float4* y;
                y = (float4*)(g_Y2 + ((size_t)s * NSIDE + 0) * NSIDE + 4 * t);
                y[0] = make_float4(gr[0][0], gi[0][0], gr[0][1], gi[0][1]);
                y[1] = make_float4(gr[0][2], gi[0][2], gr[0][3], gi[0][3]);
                y = (float4*)(g_Y2 + ((size_t)s * NSIDE + 64) * NSIDE + 4 * t);
                y[0] = make_float4(gr[1][0], gi[1][0], gr[1][1], gi[1][1]);
                y[1] = make_float4(gr[1][2], gi[1][2], gr[1][3], gi[1][3]);
            }
        }
    }
}

// ---------------------------------------------------------------------------
// P2: per (slice, 32-m tile). Interleaved float2 tiles T1/T2[128*33],
// float4 global loads, NF=2 inverse FFT, fused fast epilogue.
// ---------------------------------------------------------------------------
__global__ void __launch_bounds__(512, 2) p2_kernel(float* __restrict__ out,
                                                    const float* __restrict__ df,
                                                    const float* __restrict__ d2f)
{
    extern __shared__ float2 smc[];
    float2* T1 = smc;            // 128*33 float2
    float2* T2 = smc + 4224;

    const int s    = blockIdx.x;
    const int m0   = blockIdx.y * 32;
    const int tid  = threadIdx.x;
    const int u    = tid >> 5;
    const int t    = tid & 31;

    Tw T;
    make_tw(T, t);

    const float4* y1v = (const float4*)(g_Y1 + (size_t)s * (NSIDE * NSIDE));
    const float4* y2v = (const float4*)(g_Y2 + (size_t)s * (NSIDE * NSIDE));
    const int mb = blockIdx.y * 16;

#pragma unroll
    for (int i = 0; i < 4; ++i) {
        int e  = i * 512 + tid;
        int q  = e >> 4;
        int mp = e & 15;
        float4 v1 = y1v[q * 64 + mb + mp];
        T1[q * 33 + 2 * mp]     = make_float2(v1.x, v1.y);
        T1[q * 33 + 2 * mp + 1] = make_float2(v1.z, v1.w);
        float4 v2 = y2v[q * 64 + mb + mp];
        T2[q * 33 + 2 * mp]     = make_float2(v2.x, v2.y);
        T2[q * 33 + 2 * mp + 1] = make_float2(v2.z, v2.w);
    }
    __syncthreads();

    const int c = s & 63;
    float df0 = df[2 * c], df1 = df[2 * c + 1];
    float ed  = expf(df0);
    float dfcr = ed * cosf(df1), dfci = ed * sinf(df1);
    float d20 = d2f[2 * c], d21 = d2f[2 * c + 1];
    float inv_nf = 0.5f / (dfcr * dfcr + dfci * dfci);
    float hrr = (d20 * dfcr + d21 * dfci) * inv_nf;
    float hri = (d21 * dfcr - d20 * dfci) * inv_nf;

    const float EPS2   = 1e-6f;
    const float LN_EPS = -6.9077552790f;
    const float TR_MIN = -2.5902671570f;

#pragma unroll 1
    for (int iter = 0; iter < 2; ++iter) {
        int mm = iter * 16 + u;
        int m  = m0 + mm;

        float vr[2][4], vi[2][4];
#pragma unroll
        for (int k1 = 0; k1 < 4; ++k1) {
            int qs = t + (k1 << 5);
            float2 a = T1[qs * 33 + mm];
            vr[0][k1] = a.x;
            vi[0][k1] = a.y;
            float2 b = T2[qs * 33 + mm];
            vr[1][k1] = b.x;
            vi[1][k1] = b.y;
        }
        fft_inv_n<2>(vr, vi, T, t);

        float oh[4], oa[4], op[4], ot[4], os[4];
#pragma unroll
        for (int j = 0; j < 4; ++j) {
            float Dr0 = vr[0][j], Di0 = vi[0][j];
            float d2r = vr[1][j], d2i = vi[1][j];

            float h = Dr0 * Dr0 + Di0 * Di0;
            bool valid = (h >= EPS2);
            float Dr = valid ? Dr0 : 1.0f;
            float Di = valid ? Di0 : 0.0f;
            float nD = valid ? h : 1.0f;

            float lnA = 0.0f, Phi = 0.0f;
            if (valid) {
                float la = df0 - 0.5f * __logf(h);
                lnA = fminf(3.0f, fmaxf(-3.0f, la));
                float a2r = dfcr * Dr + dfci * Di;
                float a2i = dfci * Dr - dfcr * Di;
                Phi = fatan2f(a2i, a2r);
            }

            float t1r = d2r * dfcr - d2i * dfci;
            float t1i = d2r * dfci + d2i * dfcr;
            float D2r = Dr * Dr - Di * Di;
            float D2i = 2.0f * Dr * Di;
            float inv2h = 0.5f * __fdividef(1.0f, nD * nD);
            float anr = (t1r * D2r + t1i * D2i) * inv2h - hrr;
            float ani = (t1i * D2r - t1r * D2i) * inv2h - hri;

            float na = anr * anr + ani * ani;
            bool tm = valid && (na >= EPS2);
            float lnT = LN_EPS, Psi = 0.0f;
            if (tm) {
                float lt = 0.5f * __logf(na);
                lnT = fminf(3.0f, fmaxf(TR_MIN, lt));
                Psi = fatan2f(ani, anr);
            }

            oh[j] = h; oa[j] = lnA; op[j] = Phi; ot[j] = lnT; os[j] = Psi;
        }

        size_t base = (size_t)s * 16384 + (size_t)m * 128;
        ((float4*)(out + base))[t]             = *(float4*)oh;
        ((float4*)(out + PLANE + base))[t]     = *(float4*)oa;
        ((float4*)(out + 2 * PLANE + base))[t] = *(float4*)op;
        ((float4*)(out + 3 * PLANE + base))[t] = *(float4*)ot;
        ((float4*)(out + 4 * PLANE + base))[t] = *(float4*)os;
    }
}

extern "C" void kernel_launch(void* const* d_in, const int* in_sizes, int n_in,
                              void* d_out, int out_size)
{
    const float* x   = (const float*)d_in[0];
    const float* df  = (const float*)d_in[1];
    const float* d2f = (const float*)d_in[2];
    float* out = (float*)d_out;

    const int P1_SMEM = (128 * 64 + 128) * 8;   // 66560 B
    const int P2_SMEM = 2 * 4224 * 8;           // 67584 B

    cudaFuncSetAttribute(p1_kernel, cudaFuncAttributeMaxDynamicSharedMemorySize, P1_SMEM);
    cudaFuncSetAttribute(p2_kernel, cudaFuncAttributeMaxDynamicSharedMemorySize, P2_SMEM);

    p1_kernel<<<SLICES, 256, P1_SMEM>>>(x);
    p2_kernel<<<dim3(SLICES, 4), 512, P2_SMEM>>>(out, df, d2f);
}